// round 9
// baseline (speedup 1.0000x reference)
#include <cuda_runtime.h>
#include <cuda_fp16.h>
#include <cstdint>

#define Hc 128
#define Wc 128
#define Cc 64
#define COUTc 64
#define Bc 4
#define NPIX (Bc*Hc*Wc)

// ------------------------------ scratch ------------------------------------
__device__ uint4  g_xH4[NPIX*8];        // NHWC fp16 input (8 uint4 = 64c/px)
__device__ float2 g_offs2[9*NPIX];      // offsets [tap][pix] (dy,dx)
__device__ uint4  g_wH4[9*512];         // main weights fp16 [tap][c64][co64]

// ------------------------------ helpers ------------------------------------
__device__ __forceinline__ void mma16(float* d, const uint32_t* a,
                                      uint32_t b0, uint32_t b1) {
    asm volatile(
        "mma.sync.aligned.m16n8k16.row.col.f32.f16.f16.f32 "
        "{%0,%1,%2,%3}, {%4,%5,%6,%7}, {%8,%9}, {%0,%1,%2,%3};"
        : "+f"(d[0]), "+f"(d[1]), "+f"(d[2]), "+f"(d[3])
        : "r"(a[0]), "r"(a[1]), "r"(a[2]), "r"(a[3]), "r"(b0), "r"(b1));
}
__device__ __forceinline__ void ldsm_x4(uint32_t* r, uint32_t a) {
    asm volatile("ldmatrix.sync.aligned.m8n8.x4.shared.b16 {%0,%1,%2,%3}, [%4];"
        : "=r"(r[0]), "=r"(r[1]), "=r"(r[2]), "=r"(r[3]) : "r"(a));
}
__device__ __forceinline__ void ldsm_x4t(uint32_t* r, uint32_t a) {
    asm volatile("ldmatrix.sync.aligned.m8n8.x4.trans.shared.b16 {%0,%1,%2,%3}, [%4];"
        : "=r"(r[0]), "=r"(r[1]), "=r"(r[2]), "=r"(r[3]) : "r"(a));
}
__device__ __forceinline__ void ldsm_x2t(uint32_t* r, uint32_t a) {
    asm volatile("ldmatrix.sync.aligned.m8n8.x2.trans.shared.b16 {%0,%1}, [%2];"
        : "=r"(r[0]), "=r"(r[1]) : "r"(a));
}
__device__ __forceinline__ uint32_t h2u(half2 h) {
    return *(uint32_t*)&h;
}

// ---------------------------------------------------------------------------
// Kernel 1 (merged prep + offset conv, no intra-launch dependencies):
//   blocks [0,512):    NCHW -> NHWC fp16 transpose of x  (writes g_xH4)
//   blocks [512,528):  main-weight rearrangement          (writes g_wH4)
//   blocks [528,1040): offset conv reading NCHW directly  (writes g_offs2)
// ---------------------------------------------------------------------------
__global__ void __launch_bounds__(256) prep_offset_kernel(
    const float* __restrict__ x, const float* __restrict__ w,
    const float* __restrict__ ow, const float* __restrict__ ob)
{
    extern __shared__ uint32_t smw[];
    int bid = blockIdx.x, tid = threadIdx.x;

    if (bid < 512) {
        // ---------------- transpose branch ----------------
        float4* sm4 = (float4*)smw;      // 2048 float4 = 32 KB
        int b = bid >> 7, y = bid & 127;
        const float4* xin = (const float4*)x;
        #pragma unroll
        for (int i = 0; i < 8; ++i) {
            int j4 = tid + 256 * i;
            int c = j4 >> 5, x4 = j4 & 31;
            int key = (c ^ (c >> 3)) & 7;
            sm4[c * 32 + (x4 ^ key)] =
                xin[((size_t)(b * Cc + c) * Hc + y) * 32 + x4];
        }
        __syncthreads();
        const float* smf = (const float*)sm4;
        #pragma unroll
        for (int i = 0; i < 4; ++i) {
            int j = tid + 256 * i;
            int grp = j & 7, px = j >> 3;
            float f[8];
            #pragma unroll
            for (int e = 0; e < 8; ++e) {
                int c = grp * 8 + e;
                int key = (c ^ (c >> 3)) & 7;
                f[e] = smf[c * 128 + 4 * ((px >> 2) ^ key) + (px & 3)];
            }
            uint4 r; half2* hr = (half2*)&r;
            hr[0] = __floats2half2_rn(f[0], f[1]);
            hr[1] = __floats2half2_rn(f[2], f[3]);
            hr[2] = __floats2half2_rn(f[4], f[5]);
            hr[3] = __floats2half2_rn(f[6], f[7]);
            g_xH4[((size_t)(b * Hc + y) * Wc + px) * 8 + grp] = r;
        }
        return;
    }
    if (bid < 528) {
        // ---------------- main weight branch ----------------
        int t = (bid - 512) * 256 + tid;            // 0..4095
        half* wh = (half*)g_wH4;                    // [tap][c][co]
        for (int idx = t; idx < 9 * 64 * 64; idx += 16 * 256) {
            int tap = idx >> 12, r = idx & 4095;
            int c = r >> 6, co = r & 63;
            wh[idx] = __float2half(w[(co * Cc + c) * 9 + tap]);
        }
        return;
    }

    // ---------------- offset conv branch (reads NCHW x directly) ----------
    // smem words: xrow[130][36] @0 (4680) | owsm[3tap][64c][12] @4680 (2304)
    uint32_t sb = (uint32_t)__cvta_generic_to_shared(smw);
    int warp = tid >> 5, lane = tid & 31;
    int g = lane >> 2, tg = lane & 3;
    int l = lane & 7, h8 = (lane >> 3) & 1, kh = (lane >> 4) & 1;
    int m = lane >> 3;
    int blk = bid - 528, b = blk >> 7, y = blk & 127;

    uint32_t a_lane = (uint32_t)((8 * h8 + l) * 36 + 4 * kh) * 4;
    uint32_t b_lane01 = (uint32_t)(4680 * 4) +
        (uint32_t)((8 * (m & 1) + l) * 12 + (m >> 1) * 4) * 4;
    uint32_t b_lane2  = (uint32_t)(4680 * 4) +
        (uint32_t)((8 * h8 + l) * 12 + 8) * 4;

    float acc[3][4];
    #pragma unroll
    for (int nt = 0; nt < 3; ++nt) {
        int col = 8 * nt + 2 * tg;
        float b0 = (col < 18) ? __ldg(&ob[col]) : 0.f;
        float b1 = (col + 1 < 18) ? __ldg(&ob[col + 1]) : 0.f;
        acc[nt][0] = b0; acc[nt][1] = b1; acc[nt][2] = b0; acc[nt][3] = b1;
    }

    for (int ky = 0; ky < 3; ++ky) {
        int yy = y + ky - 1;
        if (yy < 0 || yy >= Hc) continue;   // uniform per block
        __syncthreads();
        // stage padded fp16 input row from NCHW fp32 (coalesced per channel)
        {
            int wq = tid >> 5;               // word group 0..7
            const float* xr = x + ((size_t)(b * Cc) * Hc + yy) * Wc;
            #pragma unroll
            for (int j = 0; j < 4; ++j) {
                int wd = wq + 8 * j;         // word 0..31 -> channels 2wd,2wd+1
                const float* c0 = xr + (size_t)(2 * wd) * (Hc * Wc);
                const float* c1 = c0 + (Hc * Wc);
                #pragma unroll
                for (int t5 = 0; t5 < 5; ++t5) {
                    int xi = lane + 32 * t5;
                    if (xi < 130) {
                        int xx = xi - 1;
                        float v0 = 0.f, v1 = 0.f;
                        if (xx >= 0 && xx < Wc) { v0 = c0[xx]; v1 = c1[xx]; }
                        smw[xi * 36 + wd] = h2u(__floats2half2_rn(v0, v1));
                    }
                }
            }
        }
        // stage 3 taps of offset weights [c][24] from raw fp32 ow
        for (int idx = tid; idx < 2304; idx += 256) {
            int tap = idx / 768, r = idx - tap * 768;
            int c = r / 12, wd = r - c * 12;
            int o0 = 2 * wd, tgl = ky * 3 + tap;
            float v0 = (o0 < 18) ? ow[(o0 * Cc + c) * 9 + tgl] : 0.f;
            float v1 = (o0 + 1 < 18) ? ow[((o0 + 1) * Cc + c) * 9 + tgl] : 0.f;
            smw[4680 + idx] = h2u(__floats2half2_rn(v0, v1));
        }
        __syncthreads();
        #pragma unroll
        for (int kx = 0; kx < 3; ++kx) {
            uint32_t abase = sb + (uint32_t)((warp * 16 + kx) * 36) * 4 + a_lane;
            uint32_t bb01  = sb + (uint32_t)(kx * 768) * 4 + b_lane01;
            uint32_t bb2   = sb + (uint32_t)(kx * 768) * 4 + b_lane2;
            #pragma unroll
            for (int kk = 0; kk < 4; ++kk) {
                uint32_t a[4], bq[4], b2[2];
                ldsm_x4(a, abase + kk * 32);
                ldsm_x4t(bq, bb01 + kk * 768);
                ldsm_x2t(b2, bb2 + kk * 768);
                mma16(acc[0], a, bq[0], bq[1]);
                mma16(acc[1], a, bq[2], bq[3]);
                mma16(acc[2], a, b2[0], b2[1]);
            }
        }
    }

    int pix0 = blk * 128;
    #pragma unroll
    for (int nt = 0; nt < 3; ++nt) {
        int col = 8 * nt + 2 * tg;
        if (col < 18) {
            int tap = col >> 1;
            int p = warp * 16 + g;
            g_offs2[(size_t)tap * NPIX + pix0 + p] =
                make_float2(acc[nt][0], acc[nt][1]);
            g_offs2[(size_t)tap * NPIX + pix0 + p + 8] =
                make_float2(acc[nt][2], acc[nt][3]);
        }
    }
}

// ---------------------------------------------------------------------------
// Kernel 2: fused deformable sampling + fp16 mma GEMM.
// Block = 64 px x 64 co, 128 threads (4 warps), warp tile 32px x 32co.
// 6 blocks/SM (85-reg budget, same as proven spill-free (256,3) build).
// smem words: patch[2][64][36] @0 (4608) | wsm[2][64c][36] @4608 (4608)
// total 9216 words = 36864 B.
// ---------------------------------------------------------------------------
__global__ void __launch_bounds__(128, 6) dcn_main_kernel(
    const float* __restrict__ bias, float* __restrict__ out)
{
    extern __shared__ uint32_t smw[];
    uint32_t sb = (uint32_t)__cvta_generic_to_shared(smw);

    int tid = threadIdx.x, warp = tid >> 5, lane = tid & 31;
    int g = lane >> 2, tg = lane & 3;
    int l = lane & 7, h8 = (lane >> 3) & 1, kh = (lane >> 4) & 1;
    int m = lane >> 3;
    int mgrp = warp >> 1, ngrp = warp & 1;
    int blk = blockIdx.x;                 // 1024 blocks of 64 px
    int px0 = blk << 6;
    int b = px0 >> 14, y = (px0 >> 7) & 127, x0 = px0 & 127;
    int s_cg = tid & 7, s_p0 = tid >> 3;  // 16 pixel slots

    uint32_t a_lane = (uint32_t)((mgrp * 32 + 8 * h8 + l) * 36 + 4 * kh) * 4;
    uint32_t b_lane = (uint32_t)((8 * (m & 1) + l) * 36 +
                                 (ngrp * 4 + (m >> 1)) * 4) * 4;

    float acc[2][4][4];
    #pragma unroll
    for (int mt = 0; mt < 2; ++mt)
        #pragma unroll
        for (int nt = 0; nt < 4; ++nt)
            #pragma unroll
            for (int j = 0; j < 4; ++j) acc[mt][nt][j] = 0.f;

    // prefetch tap-0 offsets
    float2 o2[4];
    #pragma unroll
    for (int i = 0; i < 4; ++i)
        o2[i] = __ldg(&g_offs2[(size_t)px0 + s_p0 + 16 * i]);

    for (int k = 0; k < 9; ++k) {
        int buf = k & 1;
        // stage weight tile [c][co] fp16 into wsm[buf], 36-word row pitch
        {
            uint4* dst = (uint4*)(smw + 4608 + buf * 2304);
            const uint4* src = g_wH4 + k * 512;
            #pragma unroll
            for (int i = 0; i < 4; ++i) {
                int j4 = tid + 128 * i;
                int c = j4 >> 3, seg = j4 & 7;
                dst[c * 9 + seg] = src[j4];
            }
        }
        // sample into patch[buf]
        {
            uint4* pdst = (uint4*)(smw + buf * 2304);
            int ky = k / 3, kx = k - ky * 3;
            #pragma unroll
            for (int i = 0; i < 4; ++i) {
                int p = s_p0 + 16 * i;
                float2 d2 = o2[i];
                float py  = (float)(y - 1 + ky) + d2.x;
                float pxx = (float)(x0 + p - 1 + kx) + d2.y;
                float fy = floorf(py), fx = floorf(pxx);
                float ly = py - fy, lx = pxx - fx;
                int y0 = (int)fy, xq = (int)fx;
                bool vy0 = (y0 >= 0) & (y0 < Hc);
                bool vy1 = (y0 + 1 >= 0) & (y0 + 1 < Hc);
                bool vx0 = (xq >= 0) & (xq < Wc);
                bool vx1 = (xq + 1 >= 0) & (xq + 1 < Wc);
                float w00 = (1.f - ly) * (1.f - lx) * (float)(vy0 && vx0);
                float w01 = (1.f - ly) * lx         * (float)(vy0 && vx1);
                float w10 = ly * (1.f - lx)         * (float)(vy1 && vx0);
                float w11 = ly * lx                 * (float)(vy1 && vx1);
                int yc0 = min(max(y0, 0), Hc - 1);
                int yc1 = min(max(y0 + 1, 0), Hc - 1);
                int xc0 = min(max(xq, 0), Wc - 1);
                int xc1 = min(max(xq + 1, 0), Wc - 1);
                int r0 = (b * Hc + yc0) * Wc, r1 = (b * Hc + yc1) * Wc;
                uint4 q00 = g_xH4[(size_t)(r0 + xc0) * 8 + s_cg];
                uint4 q01 = g_xH4[(size_t)(r0 + xc1) * 8 + s_cg];
                uint4 q10 = g_xH4[(size_t)(r1 + xc0) * 8 + s_cg];
                uint4 q11 = g_xH4[(size_t)(r1 + xc1) * 8 + s_cg];
                const half2* h00 = (const half2*)&q00;
                const half2* h01 = (const half2*)&q01;
                const half2* h10 = (const half2*)&q10;
                const half2* h11 = (const half2*)&q11;
                uint4 r;
                half2* hr = (half2*)&r;
                #pragma unroll
                for (int j = 0; j < 4; ++j) {
                    float2 f00 = __half22float2(h00[j]);
                    float2 f01 = __half22float2(h01[j]);
                    float2 f10 = __half22float2(h10[j]);
                    float2 f11 = __half22float2(h11[j]);
                    float rx = w00*f00.x + w01*f01.x + w10*f10.x + w11*f11.x;
                    float ry = w00*f00.y + w01*f01.y + w10*f10.y + w11*f11.y;
                    hr[j] = __floats2half2_rn(rx, ry);
                }
                pdst[p * 9 + s_cg] = r;
            }
            // prefetch next tap's offsets
            if (k < 8) {
                #pragma unroll
                for (int i = 0; i < 4; ++i)
                    o2[i] = __ldg(&g_offs2[(size_t)(k + 1) * NPIX +
                                           px0 + s_p0 + 16 * i]);
            }
        }
        __syncthreads();
        // GEMM via ldmatrix
        {
            uint32_t abase = sb + (uint32_t)(buf * 2304) * 4 + a_lane;
            uint32_t bbase = sb + (uint32_t)((4608 + buf * 2304)) * 4 + b_lane;
            #pragma unroll
            for (int kk = 0; kk < 4; ++kk) {
                uint32_t a0[4], a1[4], bq0[4], bq1[4];
                ldsm_x4(a0, abase + kk * 32);
                ldsm_x4(a1, abase + 2304 + kk * 32);     // +16 rows
                ldsm_x4t(bq0, bbase + kk * 2304);        // +16 c-rows per kk
                ldsm_x4t(bq1, bbase + 32 + kk * 2304);
                mma16(acc[0][0], a0, bq0[0], bq0[1]);
                mma16(acc[0][1], a0, bq0[2], bq0[3]);
                mma16(acc[0][2], a0, bq1[0], bq1[1]);
                mma16(acc[0][3], a0, bq1[2], bq1[3]);
                mma16(acc[1][0], a1, bq0[0], bq0[1]);
                mma16(acc[1][1], a1, bq0[2], bq0[3]);
                mma16(acc[1][2], a1, bq1[0], bq1[1]);
                mma16(acc[1][3], a1, bq1[2], bq1[3]);
            }
        }
    }

    // epilogue: transpose through smem (stride 68), add bias, store NCHW
    __syncthreads();
    float* O = (float*)smw;   // 64*68 = 4352 floats < 9216 words
    #pragma unroll
    for (int mt = 0; mt < 2; ++mt)
        #pragma unroll
        for (int nt = 0; nt < 4; ++nt) {
            int row = mgrp * 32 + 16 * mt + g;
            int col = ngrp * 32 + 8 * nt + 2 * tg;
            float b0 = __ldg(&bias[col]), b1 = __ldg(&bias[col + 1]);
            O[col * 68 + row]           = acc[mt][nt][0] + b0;
            O[(col + 1) * 68 + row]     = acc[mt][nt][1] + b1;
            O[col * 68 + row + 8]       = acc[mt][nt][2] + b0;
            O[(col + 1) * 68 + row + 8] = acc[mt][nt][3] + b1;
        }
    __syncthreads();
    #pragma unroll
    for (int i = 0; i < 8; ++i) {
        int j4 = tid + 128 * i;          // 1024 float4s = 64co x 16
        int co = j4 >> 4, xq = j4 & 15;
        float4 v = *(float4*)&O[co * 68 + xq * 4];
        *(float4*)&out[(((size_t)b * COUTc + co) * Hc + y) * Wc + x0 + xq * 4] = v;
    }
}

// ---------------------------------------------------------------------------
extern "C" void kernel_launch(void* const* d_in, const int* in_sizes, int n_in,
                              void* d_out, int out_size)
{
    const float* x      = (const float*)d_in[0];
    const float* weight = (const float*)d_in[1];
    const float* bias   = (const float*)d_in[2];
    const float* ow     = (const float*)d_in[3];
    const float* ob     = (const float*)d_in[4];
    float* out = (float*)d_out;

    static int configured = 0;
    if (!configured) {
        cudaFuncSetAttribute(prep_offset_kernel,
            cudaFuncAttributeMaxDynamicSharedMemorySize, 32768);
        cudaFuncSetAttribute(dcn_main_kernel,
            cudaFuncAttributeMaxDynamicSharedMemorySize, 36864);
        configured = 1;
    }

    prep_offset_kernel<<<1040, 256, 32768>>>(x, weight, ow, ob);
    dcn_main_kernel<<<NPIX / 64, 128, 36864>>>(bias, out);
}

// round 10
// speedup vs baseline: 1.4805x; 1.4805x over previous
#include <cuda_runtime.h>
#include <cuda_fp16.h>
#include <cstdint>

#define Hc 128
#define Wc 128
#define Cc 64
#define COUTc 64
#define Bc 4
#define NPIX (Bc*Hc*Wc)

// ------------------------------ scratch ------------------------------------
__device__ uint4  g_xH4[NPIX*8];        // NHWC fp16 input (8 uint4 = 64c/px)
__device__ uint4  g_wH4[9*512];         // main weights fp16 [tap][c64][co64]
__device__ uint4  g_owH4[9*192];        // offset weights fp16 [tap][c64][o24]

// ------------------------------ helpers ------------------------------------
__device__ __forceinline__ void mma16(float* d, const uint32_t* a,
                                      uint32_t b0, uint32_t b1) {
    asm volatile(
        "mma.sync.aligned.m16n8k16.row.col.f32.f16.f16.f32 "
        "{%0,%1,%2,%3}, {%4,%5,%6,%7}, {%8,%9}, {%0,%1,%2,%3};"
        : "+f"(d[0]), "+f"(d[1]), "+f"(d[2]), "+f"(d[3])
        : "r"(a[0]), "r"(a[1]), "r"(a[2]), "r"(a[3]), "r"(b0), "r"(b1));
}
__device__ __forceinline__ void ldsm_x4(uint32_t* r, uint32_t a) {
    asm volatile("ldmatrix.sync.aligned.m8n8.x4.shared.b16 {%0,%1,%2,%3}, [%4];"
        : "=r"(r[0]), "=r"(r[1]), "=r"(r[2]), "=r"(r[3]) : "r"(a));
}
__device__ __forceinline__ void ldsm_x4t(uint32_t* r, uint32_t a) {
    asm volatile("ldmatrix.sync.aligned.m8n8.x4.trans.shared.b16 {%0,%1,%2,%3}, [%4];"
        : "=r"(r[0]), "=r"(r[1]), "=r"(r[2]), "=r"(r[3]) : "r"(a));
}
__device__ __forceinline__ void ldsm_x2t(uint32_t* r, uint32_t a) {
    asm volatile("ldmatrix.sync.aligned.m8n8.x2.trans.shared.b16 {%0,%1}, [%2];"
        : "=r"(r[0]), "=r"(r[1]) : "r"(a));
}

// ---------------------------------------------------------------------------
// Kernel 1: prep. blocks 0..511: NCHW->NHWC fp16 transpose (xor-swizzled,
// vectorized both phases); 512+: weight rearrangement (both convs).
// ---------------------------------------------------------------------------
__global__ void __launch_bounds__(256) prep_kernel(
    const float* __restrict__ x, const float* __restrict__ w,
    const float* __restrict__ ow)
{
    int bid = blockIdx.x, tid = threadIdx.x;
    if (bid < 512) {
        __shared__ float4 sm4[2048];     // 64c x 32 float4, xor-swizzled
        int b = bid >> 7, y = bid & 127;
        const float4* xin = (const float4*)x;
        #pragma unroll
        for (int i = 0; i < 8; ++i) {
            int j4 = tid + 256 * i;
            int c = j4 >> 5, x4 = j4 & 31;
            int key = (c ^ (c >> 3)) & 7;
            sm4[c * 32 + (x4 ^ key)] =
                xin[((size_t)(b * Cc + c) * Hc + y) * 32 + x4];
        }
        __syncthreads();
        const float* smf = (const float*)sm4;
        #pragma unroll
        for (int i = 0; i < 4; ++i) {
            int j = tid + 256 * i;
            int grp = j & 7, px = j >> 3;
            float f[8];
            #pragma unroll
            for (int e = 0; e < 8; ++e) {
                int c = grp * 8 + e;
                int key = (c ^ (c >> 3)) & 7;
                f[e] = smf[c * 128 + 4 * ((px >> 2) ^ key) + (px & 3)];
            }
            uint4 r; half2* hr = (half2*)&r;
            hr[0] = __floats2half2_rn(f[0], f[1]);
            hr[1] = __floats2half2_rn(f[2], f[3]);
            hr[2] = __floats2half2_rn(f[4], f[5]);
            hr[3] = __floats2half2_rn(f[6], f[7]);
            g_xH4[((size_t)(b * Hc + y) * Wc + px) * 8 + grp] = r;
        }
    } else {
        int t = (bid - 512) * 256 + tid;
        half* wh = (half*)g_wH4;                    // [tap][c][co]
        for (int idx = t; idx < 9 * 64 * 64; idx += 36 * 256) {
            int tap = idx >> 12, r = idx & 4095;
            int c = r >> 6, co = r & 63;
            wh[idx] = __float2half(w[(co * Cc + c) * 9 + tap]);
        }
        half* oh = (half*)g_owH4;                   // [tap][c][24]
        for (int idx = t; idx < 9 * 64 * 24; idx += 36 * 256) {
            int tap = idx / 1536;
            int r = idx - tap * 1536;
            int c = r / 24, o = r - c * 24;
            oh[idx] = (o < 18) ? __float2half(ow[(o * Cc + c) * 9 + tap])
                               : __float2half(0.f);
        }
    }
}

// ---------------------------------------------------------------------------
// Kernel 2: FUSED offset conv + deformable sampling + fp16 mma GEMM.
// Block = 1 image row (128 px) x 64 co, 256 threads (8 warps), 3 blocks/SM.
//
// Phase A (offset conv): warp tile 16px x 24ch over 3x3 taps, reading
//   xrow staged from g_xH4 (vectorized) and owsm from g_owH4. Offsets
//   written to SMEM (no gmem round-trip).
// Phase B (main): per tap: stage W, sample via offsets-in-smem, ldmatrix GEMM.
//
// smem words: patch[2][128][36] @0 (9216) | wsm[2][64][36] @9216 (4608)
//             offs[9][128]x2     @13824 (2304)   total 16128 w = 64512 B
// Phase A aliases: xrow @0 (4680 w), owsm @9216 (2304 w)
// ---------------------------------------------------------------------------
#define SM_OFFS 13824
__global__ void __launch_bounds__(256, 3) dcn_fused_kernel(
    const float* __restrict__ ob, const float* __restrict__ bias,
    float* __restrict__ out)
{
    extern __shared__ uint32_t smw[];
    uint32_t sb = (uint32_t)__cvta_generic_to_shared(smw);

    int tid = threadIdx.x, warp = tid >> 5, lane = tid & 31;
    int g = lane >> 2, tg = lane & 3;
    int l = lane & 7, h8 = (lane >> 3) & 1, kh = (lane >> 4) & 1;
    int m = lane >> 3;
    int blk = blockIdx.x, b = blk >> 7, y = blk & 127;

    // ======================= Phase A: offset conv ==========================
    {
        uint32_t a_lane = (uint32_t)((8 * h8 + l) * 36 + 4 * kh) * 4;
        uint32_t b_lane01 = (uint32_t)(9216 * 4) +
            (uint32_t)((8 * (m & 1) + l) * 12 + (m >> 1) * 4) * 4;
        uint32_t b_lane2  = (uint32_t)(9216 * 4) +
            (uint32_t)((8 * h8 + l) * 12 + 8) * 4;

        float acc3[3][4];
        #pragma unroll
        for (int nt = 0; nt < 3; ++nt) {
            int col = 8 * nt + 2 * tg;
            float b0 = (col < 18) ? __ldg(&ob[col]) : 0.f;
            float b1 = (col + 1 < 18) ? __ldg(&ob[col + 1]) : 0.f;
            acc3[nt][0] = b0; acc3[nt][1] = b1;
            acc3[nt][2] = b0; acc3[nt][3] = b1;
        }

        for (int ky = 0; ky < 3; ++ky) {
            int yy = y + ky - 1;
            if (yy < 0 || yy >= Hc) continue;   // uniform per block
            __syncthreads();
            // stage padded fp16 input row (130 px x 8 uint4) from g_xH4
            uint4* xd = (uint4*)smw;
            #pragma unroll
            for (int i = 0; i < 5; ++i) {
                int j4 = tid + 256 * i;
                if (j4 < 1040) {
                    int xi = j4 >> 3, cg = j4 & 7, x = xi - 1;
                    uint4 v = make_uint4(0u, 0u, 0u, 0u);
                    if (x >= 0 && x < Wc)
                        v = g_xH4[((size_t)(b * Hc + yy) * Wc + x) * 8 + cg];
                    xd[xi * 9 + cg] = v;
                }
            }
            // stage 3 taps of offset weights [c][24] (12-word rows)
            {
                uint4* od = (uint4*)(smw + 9216);
                #pragma unroll
                for (int i = 0; i < 3; ++i) {
                    int j4 = tid + 256 * i;
                    if (j4 < 576) od[j4] = g_owH4[ky * 576 + j4];
                }
            }
            __syncthreads();
            #pragma unroll
            for (int kx = 0; kx < 3; ++kx) {
                uint32_t abase = sb + (uint32_t)((warp * 16 + kx) * 36) * 4 + a_lane;
                uint32_t bb01  = sb + (uint32_t)(kx * 768) * 4 + b_lane01;
                uint32_t bb2   = sb + (uint32_t)(kx * 768) * 4 + b_lane2;
                #pragma unroll
                for (int kk = 0; kk < 4; ++kk) {
                    uint32_t a[4], bq[4], b2[2];
                    ldsm_x4(a, abase + kk * 32);
                    ldsm_x4t(bq, bb01 + kk * 768);
                    ldsm_x2t(b2, bb2 + kk * 768);
                    mma16(acc3[0], a, bq[0], bq[1]);
                    mma16(acc3[1], a, bq[2], bq[3]);
                    mma16(acc3[2], a, b2[0], b2[1]);
                }
            }
        }
        __syncthreads();   // xrow/owsm regions free; offs region write begins
        // write offsets to SMEM offs[tap][pix] (float2)
        float2* offs = (float2*)(smw + SM_OFFS);
        #pragma unroll
        for (int nt = 0; nt < 3; ++nt) {
            int col = 8 * nt + 2 * tg;
            if (col < 18) {
                int tap = col >> 1;
                int p = warp * 16 + g;
                offs[tap * 128 + p]     = make_float2(acc3[nt][0], acc3[nt][1]);
                offs[tap * 128 + p + 8] = make_float2(acc3[nt][2], acc3[nt][3]);
            }
        }
        __syncthreads();
    }

    // ======================= Phase B: main conv ============================
    int mgrp = warp >> 1, ngrp = warp & 1;
    int s_cg = tid & 7, s_p0 = tid >> 3;
    const float2* offs = (const float2*)(smw + SM_OFFS);

    uint32_t a_lane = (uint32_t)((mgrp * 32 + 8 * h8 + l) * 36 + 4 * kh) * 4;
    uint32_t b_lane = (uint32_t)((8 * (m & 1) + l) * 36 +
                                 (ngrp * 4 + (m >> 1)) * 4) * 4;

    float acc[2][4][4];
    #pragma unroll
    for (int mt = 0; mt < 2; ++mt)
        #pragma unroll
        for (int nt = 0; nt < 4; ++nt)
            #pragma unroll
            for (int j = 0; j < 4; ++j) acc[mt][nt][j] = 0.f;

    for (int k = 0; k < 9; ++k) {
        int buf = k & 1;
        // stage weight tile [c][co] fp16 into wsm[buf], 36-word row pitch
        {
            uint4* dst = (uint4*)(smw + 9216 + buf * 2304);
            const uint4* src = g_wH4 + k * 512;
            #pragma unroll
            for (int i = 0; i < 2; ++i) {
                int j4 = tid + 256 * i;
                int c = j4 >> 3, seg = j4 & 7;
                dst[c * 9 + seg] = src[j4];
            }
        }
        // sample into patch[buf] (offsets from SMEM)
        {
            uint4* pdst = (uint4*)(smw + buf * 4608);
            int ky = k / 3, kx = k - ky * 3;
            #pragma unroll
            for (int i = 0; i < 4; ++i) {
                int p = s_p0 + 32 * i;
                float2 d2 = offs[k * 128 + p];
                float py  = (float)(y - 1 + ky) + d2.x;
                float pxx = (float)(p - 1 + kx) + d2.y;
                float fy = floorf(py), fx = floorf(pxx);
                float ly = py - fy, lx = pxx - fx;
                int y0 = (int)fy, xq = (int)fx;
                bool vy0 = (y0 >= 0) & (y0 < Hc);
                bool vy1 = (y0 + 1 >= 0) & (y0 + 1 < Hc);
                bool vx0 = (xq >= 0) & (xq < Wc);
                bool vx1 = (xq + 1 >= 0) & (xq + 1 < Wc);
                float w00 = (1.f - ly) * (1.f - lx) * (float)(vy0 && vx0);
                float w01 = (1.f - ly) * lx         * (float)(vy0 && vx1);
                float w10 = ly * (1.f - lx)         * (float)(vy1 && vx0);
                float w11 = ly * lx                 * (float)(vy1 && vx1);
                int yc0 = min(max(y0, 0), Hc - 1);
                int yc1 = min(max(y0 + 1, 0), Hc - 1);
                int xc0 = min(max(xq, 0), Wc - 1);
                int xc1 = min(max(xq + 1, 0), Wc - 1);
                int r0 = (b * Hc + yc0) * Wc, r1 = (b * Hc + yc1) * Wc;
                uint4 q00 = g_xH4[(size_t)(r0 + xc0) * 8 + s_cg];
                uint4 q01 = g_xH4[(size_t)(r0 + xc1) * 8 + s_cg];
                uint4 q10 = g_xH4[(size_t)(r1 + xc0) * 8 + s_cg];
                uint4 q11 = g_xH4[(size_t)(r1 + xc1) * 8 + s_cg];
                const half2* h00 = (const half2*)&q00;
                const half2* h01 = (const half2*)&q01;
                const half2* h10 = (const half2*)&q10;
                const half2* h11 = (const half2*)&q11;
                uint4 r;
                half2* hr = (half2*)&r;
                #pragma unroll
                for (int j = 0; j < 4; ++j) {
                    float2 f00 = __half22float2(h00[j]);
                    float2 f01 = __half22float2(h01[j]);
                    float2 f10 = __half22float2(h10[j]);
                    float2 f11 = __half22float2(h11[j]);
                    float rx = w00*f00.x + w01*f01.x + w10*f10.x + w11*f11.x;
                    float ry = w00*f00.y + w01*f01.y + w10*f10.y + w11*f11.y;
                    hr[j] = __floats2half2_rn(rx, ry);
                }
                pdst[p * 9 + s_cg] = r;
            }
        }
        __syncthreads();
        // GEMM via ldmatrix
        {
            uint32_t abase = sb + (uint32_t)(buf * 4608) * 4 + a_lane;
            uint32_t bbase = sb + (uint32_t)((9216 + buf * 2304)) * 4 + b_lane;
            #pragma unroll
            for (int kk = 0; kk < 4; ++kk) {
                uint32_t a0[4], a1[4], bq0[4], bq1[4];
                ldsm_x4(a0, abase + kk * 32);
                ldsm_x4(a1, abase + 2304 + kk * 32);
                ldsm_x4t(bq0, bbase + kk * 2304);
                ldsm_x4t(bq1, bbase + 32 + kk * 2304);
                mma16(acc[0][0], a0, bq0[0], bq0[1]);
                mma16(acc[0][1], a0, bq0[2], bq0[3]);
                mma16(acc[0][2], a0, bq1[0], bq1[1]);
                mma16(acc[0][3], a0, bq1[2], bq1[3]);
                mma16(acc[1][0], a1, bq0[0], bq0[1]);
                mma16(acc[1][1], a1, bq0[2], bq0[3]);
                mma16(acc[1][2], a1, bq1[0], bq1[1]);
                mma16(acc[1][3], a1, bq1[2], bq1[3]);
            }
        }
    }

    // epilogue: transpose through smem (stride 132 floats), add bias, store
    __syncthreads();
    float* O = (float*)smw;   // 64*132 = 8448 floats < 13824 words
    #pragma unroll
    for (int mt = 0; mt < 2; ++mt)
        #pragma unroll
        for (int nt = 0; nt < 4; ++nt) {
            int row = mgrp * 32 + 16 * mt + g;
            int col = ngrp * 32 + 8 * nt + 2 * tg;
            float b0 = __ldg(&bias[col]), b1 = __ldg(&bias[col + 1]);
            O[col * 132 + row]           = acc[mt][nt][0] + b0;
            O[(col + 1) * 132 + row]     = acc[mt][nt][1] + b1;
            O[col * 132 + row + 8]       = acc[mt][nt][2] + b0;
            O[(col + 1) * 132 + row + 8] = acc[mt][nt][3] + b1;
        }
    __syncthreads();
    #pragma unroll
    for (int i = 0; i < 8; ++i) {
        int j4 = tid + 256 * i;
        int co = j4 >> 5, xq = j4 & 31;
        float4 v = *(float4*)&O[co * 132 + xq * 4];
        *(float4*)&out[(((size_t)b * COUTc + co) * Hc + y) * Wc + xq * 4] = v;
    }
}

// ---------------------------------------------------------------------------
extern "C" void kernel_launch(void* const* d_in, const int* in_sizes, int n_in,
                              void* d_out, int out_size)
{
    const float* x      = (const float*)d_in[0];
    const float* weight = (const float*)d_in[1];
    const float* bias   = (const float*)d_in[2];
    const float* ow     = (const float*)d_in[3];
    const float* ob     = (const float*)d_in[4];
    float* out = (float*)d_out;

    static int configured = 0;
    if (!configured) {
        cudaFuncSetAttribute(dcn_fused_kernel,
            cudaFuncAttributeMaxDynamicSharedMemorySize, 16128 * 4);
        configured = 1;
    }

    prep_kernel<<<512 + 36, 256>>>(x, weight, ow);
    dcn_fused_kernel<<<Bc * Hc, 256, 16128 * 4>>>(ob, bias, out);
}

// round 11
// speedup vs baseline: 1.5943x; 1.0769x over previous
#include <cuda_runtime.h>
#include <cuda_fp16.h>
#include <cstdint>

#define Hc 128
#define Wc 128
#define Cc 64
#define COUTc 64
#define Bc 4
#define NPIX (Bc*Hc*Wc)

// ------------------------------ scratch ------------------------------------
__device__ uint4  g_xH4[NPIX*8];        // NHWC fp16 input (8 uint4 = 64c/px)
__device__ uint4  g_wH4[9*512];         // main weights fp16 [tap][c64][co64]
__device__ uint4  g_owH4[9*192];        // offset weights fp16 [tap][c64][o24]

// ------------------------------ helpers ------------------------------------
__device__ __forceinline__ void mma16(float* d, const uint32_t* a,
                                      uint32_t b0, uint32_t b1) {
    asm volatile(
        "mma.sync.aligned.m16n8k16.row.col.f32.f16.f16.f32 "
        "{%0,%1,%2,%3}, {%4,%5,%6,%7}, {%8,%9}, {%0,%1,%2,%3};"
        : "+f"(d[0]), "+f"(d[1]), "+f"(d[2]), "+f"(d[3])
        : "r"(a[0]), "r"(a[1]), "r"(a[2]), "r"(a[3]), "r"(b0), "r"(b1));
}
__device__ __forceinline__ void ldsm_x4(uint32_t* r, uint32_t a) {
    asm volatile("ldmatrix.sync.aligned.m8n8.x4.shared.b16 {%0,%1,%2,%3}, [%4];"
        : "=r"(r[0]), "=r"(r[1]), "=r"(r[2]), "=r"(r[3]) : "r"(a));
}
__device__ __forceinline__ void ldsm_x4t(uint32_t* r, uint32_t a) {
    asm volatile("ldmatrix.sync.aligned.m8n8.x4.trans.shared.b16 {%0,%1,%2,%3}, [%4];"
        : "=r"(r[0]), "=r"(r[1]), "=r"(r[2]), "=r"(r[3]) : "r"(a));
}
__device__ __forceinline__ void ldsm_x2t(uint32_t* r, uint32_t a) {
    asm volatile("ldmatrix.sync.aligned.m8n8.x2.trans.shared.b16 {%0,%1}, [%2];"
        : "=r"(r[0]), "=r"(r[1]) : "r"(a));
}
__device__ __forceinline__ void cp_async16(uint32_t saddr, const void* gaddr) {
    asm volatile("cp.async.cg.shared.global [%0], [%1], 16;"
        :: "r"(saddr), "l"(gaddr) : "memory");
}
#define CP_COMMIT() asm volatile("cp.async.commit_group;" ::: "memory")
#define CP_WAIT0()  asm volatile("cp.async.wait_group 0;" ::: "memory")

// ---------------------------------------------------------------------------
// Kernel 1: prep. blocks 0..511: NCHW->NHWC fp16 transpose; 512+: weights.
// ---------------------------------------------------------------------------
__global__ void __launch_bounds__(256) prep_kernel(
    const float* __restrict__ x, const float* __restrict__ w,
    const float* __restrict__ ow)
{
    int bid = blockIdx.x, tid = threadIdx.x;
    if (bid < 512) {
        __shared__ float4 sm4[2048];
        int b = bid >> 7, y = bid & 127;
        const float4* xin = (const float4*)x;
        #pragma unroll
        for (int i = 0; i < 8; ++i) {
            int j4 = tid + 256 * i;
            int c = j4 >> 5, x4 = j4 & 31;
            int key = (c ^ (c >> 3)) & 7;
            sm4[c * 32 + (x4 ^ key)] =
                xin[((size_t)(b * Cc + c) * Hc + y) * 32 + x4];
        }
        __syncthreads();
        const float* smf = (const float*)sm4;
        #pragma unroll
        for (int i = 0; i < 4; ++i) {
            int j = tid + 256 * i;
            int grp = j & 7, px = j >> 3;
            float f[8];
            #pragma unroll
            for (int e = 0; e < 8; ++e) {
                int c = grp * 8 + e;
                int key = (c ^ (c >> 3)) & 7;
                f[e] = smf[c * 128 + 4 * ((px >> 2) ^ key) + (px & 3)];
            }
            uint4 r; half2* hr = (half2*)&r;
            hr[0] = __floats2half2_rn(f[0], f[1]);
            hr[1] = __floats2half2_rn(f[2], f[3]);
            hr[2] = __floats2half2_rn(f[4], f[5]);
            hr[3] = __floats2half2_rn(f[6], f[7]);
            g_xH4[((size_t)(b * Hc + y) * Wc + px) * 8 + grp] = r;
        }
    } else {
        int t = (bid - 512) * 256 + tid;
        half* wh = (half*)g_wH4;                    // [tap][c][co]
        for (int idx = t; idx < 9 * 64 * 64; idx += 36 * 256) {
            int tap = idx >> 12, r = idx & 4095;
            int c = r >> 6, co = r & 63;
            wh[idx] = __float2half(w[(co * Cc + c) * 9 + tap]);
        }
        half* oh = (half*)g_owH4;                   // [tap][c][24]
        for (int idx = t; idx < 9 * 64 * 24; idx += 36 * 256) {
            int tap = idx / 1536;
            int r = idx - tap * 1536;
            int c = r / 24, o = r - c * 24;
            oh[idx] = (o < 18) ? __float2half(ow[(o * Cc + c) * 9 + tap])
                               : __float2half(0.f);
        }
    }
}

// ---------------------------------------------------------------------------
// Kernel 2: FUSED offset conv + deformable sampling + fp16 mma GEMM.
// Block = 1 image row (128 px) x 64 co, 256 threads, 3 blocks/SM.
// smem words: patch[2][128][36] @0 (9216) | wsm[2][64][36] @9216 (4608)
//             offs[9][128]x2 @13824 (2304) | coordbuf[2][128]x8 @16128 (2048)
// total 18176 words = 72704 B
// ---------------------------------------------------------------------------
#define SM_OFFS 13824
#define SM_CB   16128
__device__ __forceinline__ void compute_coords(
    int k, int p, int y, int b, const float2* offs, float4* cw, int4* ci)
{
    float2 d2 = offs[k * 128 + p];
    int ky = k / 3, kx = k - ky * 3;
    float py  = (float)(y - 1 + ky) + d2.x;
    float pxx = (float)(p - 1 + kx) + d2.y;
    float fy = floorf(py), fx = floorf(pxx);
    float ly = py - fy, lx = pxx - fx;
    int y0 = (int)fy, xq = (int)fx;
    bool vy0 = (y0 >= 0) & (y0 < Hc);
    bool vy1 = (y0 + 1 >= 0) & (y0 + 1 < Hc);
    bool vx0 = (xq >= 0) & (xq < Wc);
    bool vx1 = (xq + 1 >= 0) & (xq + 1 < Wc);
    float4 w4;
    w4.x = (1.f - ly) * (1.f - lx) * (float)(vy0 && vx0);
    w4.y = (1.f - ly) * lx         * (float)(vy0 && vx1);
    w4.z = ly * (1.f - lx)         * (float)(vy1 && vx0);
    w4.w = ly * lx                 * (float)(vy1 && vx1);
    int yc0 = min(max(y0, 0), Hc - 1);
    int yc1 = min(max(y0 + 1, 0), Hc - 1);
    int xc0 = min(max(xq, 0), Wc - 1);
    int xc1 = min(max(xq + 1, 0), Wc - 1);
    int r0 = (b * Hc + yc0) * Wc, r1 = (b * Hc + yc1) * Wc;
    ci[p] = make_int4((r0 + xc0) * 8, (r0 + xc1) * 8,
                      (r1 + xc0) * 8, (r1 + xc1) * 8);
    cw[p] = w4;
}

__global__ void __launch_bounds__(256, 3) dcn_fused_kernel(
    const float* __restrict__ ob, const float* __restrict__ bias,
    float* __restrict__ out)
{
    extern __shared__ uint32_t smw[];
    uint32_t sb = (uint32_t)__cvta_generic_to_shared(smw);

    int tid = threadIdx.x, warp = tid >> 5, lane = tid & 31;
    int g = lane >> 2, tg = lane & 3;
    int l = lane & 7, h8 = (lane >> 3) & 1, kh = (lane >> 4) & 1;
    int m = lane >> 3;
    int blk = blockIdx.x, b = blk >> 7, y = blk & 127;

    // ======================= Phase A: offset conv ==========================
    {
        uint32_t a_lane = (uint32_t)((8 * h8 + l) * 36 + 4 * kh) * 4;
        uint32_t b_lane01 = (uint32_t)(9216 * 4) +
            (uint32_t)((8 * (m & 1) + l) * 12 + (m >> 1) * 4) * 4;
        uint32_t b_lane2  = (uint32_t)(9216 * 4) +
            (uint32_t)((8 * h8 + l) * 12 + 8) * 4;

        float acc3[3][4];
        #pragma unroll
        for (int nt = 0; nt < 3; ++nt) {
            int col = 8 * nt + 2 * tg;
            float b0 = (col < 18) ? __ldg(&ob[col]) : 0.f;
            float b1 = (col + 1 < 18) ? __ldg(&ob[col + 1]) : 0.f;
            acc3[nt][0] = b0; acc3[nt][1] = b1;
            acc3[nt][2] = b0; acc3[nt][3] = b1;
        }

        for (int ky = 0; ky < 3; ++ky) {
            int yy = y + ky - 1;
            if (yy < 0 || yy >= Hc) continue;   // uniform per block
            __syncthreads();
            uint4* xd = (uint4*)smw;
            #pragma unroll
            for (int i = 0; i < 5; ++i) {
                int j4 = tid + 256 * i;
                if (j4 < 1040) {
                    int xi = j4 >> 3, cg = j4 & 7, x = xi - 1;
                    uint4 v = make_uint4(0u, 0u, 0u, 0u);
                    if (x >= 0 && x < Wc)
                        v = g_xH4[((size_t)(b * Hc + yy) * Wc + x) * 8 + cg];
                    xd[xi * 9 + cg] = v;
                }
            }
            {
                uint4* od = (uint4*)(smw + 9216);
                #pragma unroll
                for (int i = 0; i < 3; ++i) {
                    int j4 = tid + 256 * i;
                    if (j4 < 576) od[j4] = g_owH4[ky * 576 + j4];
                }
            }
            __syncthreads();
            #pragma unroll
            for (int kx = 0; kx < 3; ++kx) {
                uint32_t abase = sb + (uint32_t)((warp * 16 + kx) * 36) * 4 + a_lane;
                uint32_t bb01  = sb + (uint32_t)(kx * 768) * 4 + b_lane01;
                uint32_t bb2   = sb + (uint32_t)(kx * 768) * 4 + b_lane2;
                #pragma unroll
                for (int kk = 0; kk < 4; ++kk) {
                    uint32_t a[4], bq[4], b2[2];
                    ldsm_x4(a, abase + kk * 32);
                    ldsm_x4t(bq, bb01 + kk * 768);
                    ldsm_x2t(b2, bb2 + kk * 768);
                    mma16(acc3[0], a, bq[0], bq[1]);
                    mma16(acc3[1], a, bq[2], bq[3]);
                    mma16(acc3[2], a, b2[0], b2[1]);
                }
            }
        }
        __syncthreads();
        float2* offs = (float2*)(smw + SM_OFFS);
        #pragma unroll
        for (int nt = 0; nt < 3; ++nt) {
            int col = 8 * nt + 2 * tg;
            if (col < 18) {
                int tap = col >> 1;
                int p = warp * 16 + g;
                offs[tap * 128 + p]     = make_float2(acc3[nt][0], acc3[nt][1]);
                offs[tap * 128 + p + 8] = make_float2(acc3[nt][2], acc3[nt][3]);
            }
        }
        __syncthreads();
    }

    // ======================= Phase B: main conv ============================
    int mgrp = warp >> 1, ngrp = warp & 1;
    int s_cg = tid & 7, s_p0 = tid >> 3;
    const float2* offs = (const float2*)(smw + SM_OFFS);

    uint32_t a_lane = (uint32_t)((mgrp * 32 + 8 * h8 + l) * 36 + 4 * kh) * 4;
    uint32_t b_lane = (uint32_t)((8 * (m & 1) + l) * 36 +
                                 (ngrp * 4 + (m >> 1)) * 4) * 4;

    float acc[2][4][4];
    #pragma unroll
    for (int mt = 0; mt < 2; ++mt)
        #pragma unroll
        for (int nt = 0; nt < 4; ++nt)
            #pragma unroll
            for (int j = 0; j < 4; ++j) acc[mt][nt][j] = 0.f;

    // coords for tap 0 into coordbuf[0]
    if (tid < 128) {
        float4* cw = (float4*)(smw + SM_CB);
        int4*   ci = (int4*)(smw + SM_CB + 512);
        compute_coords(0, tid, y, b, offs, cw, ci);
    }
    __syncthreads();

    for (int k = 0; k < 9; ++k) {
        int buf = k & 1;
        // stage weight tile via cp.async (overlaps sampling)
        {
            const uint4* src = g_wH4 + k * 512;
            uint32_t dbase = sb + (uint32_t)(9216 + buf * 2304) * 4;
            #pragma unroll
            for (int i = 0; i < 2; ++i) {
                int j4 = tid + 256 * i;
                int c = j4 >> 3, seg = j4 & 7;
                cp_async16(dbase + (uint32_t)(c * 9 + seg) * 16, src + j4);
            }
            CP_COMMIT();
        }
        // sample into patch[buf] using coordbuf[buf]
        {
            const float4* cw = (const float4*)(smw + SM_CB + buf * 1024);
            const int4*   ci = (const int4*)(smw + SM_CB + buf * 1024 + 512);
            uint4* pdst = (uint4*)(smw + buf * 4608);
            #pragma unroll
            for (int i = 0; i < 4; ++i) {
                int p = s_p0 + 32 * i;
                float4 w4 = cw[p];
                int4   c4 = ci[p];
                uint4 q00 = g_xH4[c4.x + s_cg];
                uint4 q01 = g_xH4[c4.y + s_cg];
                uint4 q10 = g_xH4[c4.z + s_cg];
                uint4 q11 = g_xH4[c4.w + s_cg];
                const half2* h00 = (const half2*)&q00;
                const half2* h01 = (const half2*)&q01;
                const half2* h10 = (const half2*)&q10;
                const half2* h11 = (const half2*)&q11;
                uint4 r;
                half2* hr = (half2*)&r;
                #pragma unroll
                for (int j = 0; j < 4; ++j) {
                    float2 f00 = __half22float2(h00[j]);
                    float2 f01 = __half22float2(h01[j]);
                    float2 f10 = __half22float2(h10[j]);
                    float2 f11 = __half22float2(h11[j]);
                    float rx = w4.x*f00.x + w4.y*f01.x + w4.z*f10.x + w4.w*f11.x;
                    float ry = w4.x*f00.y + w4.y*f01.y + w4.z*f10.y + w4.w*f11.y;
                    hr[j] = __floats2half2_rn(rx, ry);
                }
                pdst[p * 9 + s_cg] = r;
            }
        }
        // coords for tap k+1 into coordbuf[buf^1] (before barrier; read after)
        if (k < 8 && tid < 128) {
            float4* cw = (float4*)(smw + SM_CB + (buf ^ 1) * 1024);
            int4*   ci = (int4*)(smw + SM_CB + (buf ^ 1) * 1024 + 512);
            compute_coords(k + 1, tid, y, b, offs, cw, ci);
        }
        CP_WAIT0();
        __syncthreads();
        // GEMM via ldmatrix
        {
            uint32_t abase = sb + (uint32_t)(buf * 4608) * 4 + a_lane;
            uint32_t bbase = sb + (uint32_t)((9216 + buf * 2304)) * 4 + b_lane;
            #pragma unroll
            for (int kk = 0; kk < 4; ++kk) {
                uint32_t a0[4], a1[4], bq0[4], bq1[4];
                ldsm_x4(a0, abase + kk * 32);
                ldsm_x4(a1, abase + 2304 + kk * 32);
                ldsm_x4t(bq0, bbase + kk * 2304);
                ldsm_x4t(bq1, bbase + 32 + kk * 2304);
                mma16(acc[0][0], a0, bq0[0], bq0[1]);
                mma16(acc[0][1], a0, bq0[2], bq0[3]);
                mma16(acc[0][2], a0, bq1[0], bq1[1]);
                mma16(acc[0][3], a0, bq1[2], bq1[3]);
                mma16(acc[1][0], a1, bq0[0], bq0[1]);
                mma16(acc[1][1], a1, bq0[2], bq0[3]);
                mma16(acc[1][2], a1, bq1[0], bq1[1]);
                mma16(acc[1][3], a1, bq1[2], bq1[3]);
            }
        }
    }

    // epilogue: transpose through smem (stride 132 floats), add bias, store
    __syncthreads();
    float* O = (float*)smw;
    #pragma unroll
    for (int mt = 0; mt < 2; ++mt)
        #pragma unroll
        for (int nt = 0; nt < 4; ++nt) {
            int row = mgrp * 32 + 16 * mt + g;
            int col = ngrp * 32 + 8 * nt + 2 * tg;
            float b0 = __ldg(&bias[col]), b1 = __ldg(&bias[col + 1]);
            O[col * 132 + row]           = acc[mt][nt][0] + b0;
            O[(col + 1) * 132 + row]     = acc[mt][nt][1] + b1;
            O[col * 132 + row + 8]       = acc[mt][nt][2] + b0;
            O[(col + 1) * 132 + row + 8] = acc[mt][nt][3] + b1;
        }
    __syncthreads();
    #pragma unroll
    for (int i = 0; i < 8; ++i) {
        int j4 = tid + 256 * i;
        int co = j4 >> 5, xq = j4 & 31;
        float4 v = *(float4*)&O[co * 132 + xq * 4];
        *(float4*)&out[(((size_t)b * COUTc + co) * Hc + y) * Wc + xq * 4] = v;
    }
}

// ---------------------------------------------------------------------------
extern "C" void kernel_launch(void* const* d_in, const int* in_sizes, int n_in,
                              void* d_out, int out_size)
{
    const float* x      = (const float*)d_in[0];
    const float* weight = (const float*)d_in[1];
    const float* bias   = (const float*)d_in[2];
    const float* ow     = (const float*)d_in[3];
    const float* ob     = (const float*)d_in[4];
    float* out = (float*)d_out;

    static int configured = 0;
    if (!configured) {
        cudaFuncSetAttribute(dcn_fused_kernel,
            cudaFuncAttributeMaxDynamicSharedMemorySize, 18176 * 4);
        configured = 1;
    }

    prep_kernel<<<512 + 36, 256>>>(x, weight, ow);
    dcn_fused_kernel<<<Bc * Hc, 256, 18176 * 4>>>(ob, bias, out);
}

// round 12
// speedup vs baseline: 1.6739x; 1.0499x over previous
#include <cuda_runtime.h>
#include <cuda_fp16.h>
#include <cstdint>

#define Hc 128
#define Wc 128
#define Cc 64
#define COUTc 64
#define Bc 4
#define NPIX (Bc*Hc*Wc)

// ------------------------------ scratch ------------------------------------
__device__ uint4  g_xH4[NPIX*8];        // NHWC fp16 input (8 uint4 = 64c/px)
__device__ uint4  g_wH4[9*512];         // main weights fp16 [tap][c64][co64]
__device__ uint4  g_owH4[9*192];        // offset weights fp16 [tap][c64][o24]

// ------------------------------ helpers ------------------------------------
__device__ __forceinline__ void mma16(float* d, const uint32_t* a,
                                      uint32_t b0, uint32_t b1) {
    asm volatile(
        "mma.sync.aligned.m16n8k16.row.col.f32.f16.f16.f32 "
        "{%0,%1,%2,%3}, {%4,%5,%6,%7}, {%8,%9}, {%0,%1,%2,%3};"
        : "+f"(d[0]), "+f"(d[1]), "+f"(d[2]), "+f"(d[3])
        : "r"(a[0]), "r"(a[1]), "r"(a[2]), "r"(a[3]), "r"(b0), "r"(b1));
}
__device__ __forceinline__ void ldsm_x4(uint32_t* r, uint32_t a) {
    asm volatile("ldmatrix.sync.aligned.m8n8.x4.shared.b16 {%0,%1,%2,%3}, [%4];"
        : "=r"(r[0]), "=r"(r[1]), "=r"(r[2]), "=r"(r[3]) : "r"(a));
}
__device__ __forceinline__ void ldsm_x4t(uint32_t* r, uint32_t a) {
    asm volatile("ldmatrix.sync.aligned.m8n8.x4.trans.shared.b16 {%0,%1,%2,%3}, [%4];"
        : "=r"(r[0]), "=r"(r[1]), "=r"(r[2]), "=r"(r[3]) : "r"(a));
}
__device__ __forceinline__ void ldsm_x2t(uint32_t* r, uint32_t a) {
    asm volatile("ldmatrix.sync.aligned.m8n8.x2.trans.shared.b16 {%0,%1}, [%2];"
        : "=r"(r[0]), "=r"(r[1]) : "r"(a));
}
__device__ __forceinline__ void cp_async16(uint32_t saddr, const void* gaddr) {
    asm volatile("cp.async.cg.shared.global [%0], [%1], 16;"
        :: "r"(saddr), "l"(gaddr) : "memory");
}
#define CP_COMMIT() asm volatile("cp.async.commit_group;" ::: "memory")
#define CP_WAIT0()  asm volatile("cp.async.wait_group 0;" ::: "memory")

// ---------------------------------------------------------------------------
// Kernel 1: prep. blocks 0..511: NCHW->NHWC fp16 transpose; 512+: weights.
// ---------------------------------------------------------------------------
__global__ void __launch_bounds__(256) prep_kernel(
    const float* __restrict__ x, const float* __restrict__ w,
    const float* __restrict__ ow)
{
    int bid = blockIdx.x, tid = threadIdx.x;
    if (bid < 512) {
        __shared__ float4 sm4[2048];
        int b = bid >> 7, y = bid & 127;
        const float4* xin = (const float4*)x;
        #pragma unroll
        for (int i = 0; i < 8; ++i) {
            int j4 = tid + 256 * i;
            int c = j4 >> 5, x4 = j4 & 31;
            int key = (c ^ (c >> 3)) & 7;
            sm4[c * 32 + (x4 ^ key)] =
                xin[((size_t)(b * Cc + c) * Hc + y) * 32 + x4];
        }
        __syncthreads();
        const float* smf = (const float*)sm4;
        #pragma unroll
        for (int i = 0; i < 4; ++i) {
            int j = tid + 256 * i;
            int grp = j & 7, px = j >> 3;
            float f[8];
            #pragma unroll
            for (int e = 0; e < 8; ++e) {
                int c = grp * 8 + e;
                int key = (c ^ (c >> 3)) & 7;
                f[e] = smf[c * 128 + 4 * ((px >> 2) ^ key) + (px & 3)];
            }
            uint4 r; half2* hr = (half2*)&r;
            hr[0] = __floats2half2_rn(f[0], f[1]);
            hr[1] = __floats2half2_rn(f[2], f[3]);
            hr[2] = __floats2half2_rn(f[4], f[5]);
            hr[3] = __floats2half2_rn(f[6], f[7]);
            g_xH4[((size_t)(b * Hc + y) * Wc + px) * 8 + grp] = r;
        }
    } else {
        int t = (bid - 512) * 256 + tid;
        half* wh = (half*)g_wH4;                    // [tap][c][co]
        for (int idx = t; idx < 9 * 64 * 64; idx += 36 * 256) {
            int tap = idx >> 12, r = idx & 4095;
            int c = r >> 6, co = r & 63;
            wh[idx] = __float2half(w[(co * Cc + c) * 9 + tap]);
        }
        half* oh = (half*)g_owH4;                   // [tap][c][24]
        for (int idx = t; idx < 9 * 64 * 24; idx += 36 * 256) {
            int tap = idx / 1536;
            int r = idx - tap * 1536;
            int c = r / 24, o = r - c * 24;
            oh[idx] = (o < 18) ? __float2half(ow[(o * Cc + c) * 9 + tap])
                               : __float2half(0.f);
        }
    }
}

// ---------------------------------------------------------------------------
// Kernel 2: FUSED offset conv + deformable sampling + fp16 mma GEMM.
// Block = 1 image row (128 px) x 64 co, 256 threads, 3 blocks/SM.
// Sampling lerp in packed fp16 (HFMA2 tree) with weights pre-broadcast
// as half2 in the coord buffer.
// smem words: patch[2][128][36] @0 (9216) | wsm[2][64][36] @9216 (4608)
//             offs[9][128]x2 @13824 (2304) | coordbuf[2][128]x8 @16128 (2048)
// total 18176 words = 72704 B
// ---------------------------------------------------------------------------
#define SM_OFFS 13824
#define SM_CB   16128
__device__ __forceinline__ void compute_coords(
    int k, int p, int y, int b, const float2* offs, uint4* cwh, int4* ci)
{
    float2 d2 = offs[k * 128 + p];
    int ky = k / 3, kx = k - ky * 3;
    float py  = (float)(y - 1 + ky) + d2.x;
    float pxx = (float)(p - 1 + kx) + d2.y;
    float fy = floorf(py), fx = floorf(pxx);
    float ly = py - fy, lx = pxx - fx;
    int y0 = (int)fy, xq = (int)fx;
    bool vy0 = (y0 >= 0) & (y0 < Hc);
    bool vy1 = (y0 + 1 >= 0) & (y0 + 1 < Hc);
    bool vx0 = (xq >= 0) & (xq < Wc);
    bool vx1 = (xq + 1 >= 0) & (xq + 1 < Wc);
    float w00 = (1.f - ly) * (1.f - lx) * (float)(vy0 && vx0);
    float w01 = (1.f - ly) * lx         * (float)(vy0 && vx1);
    float w10 = ly * (1.f - lx)         * (float)(vy1 && vx0);
    float w11 = ly * lx                 * (float)(vy1 && vx1);
    int yc0 = min(max(y0, 0), Hc - 1);
    int yc1 = min(max(y0 + 1, 0), Hc - 1);
    int xc0 = min(max(xq, 0), Wc - 1);
    int xc1 = min(max(xq + 1, 0), Wc - 1);
    int r0 = (b * Hc + yc0) * Wc, r1 = (b * Hc + yc1) * Wc;
    ci[p] = make_int4((r0 + xc0) * 8, (r0 + xc1) * 8,
                      (r1 + xc0) * 8, (r1 + xc1) * 8);
    uint4 wpk; half2* hp = (half2*)&wpk;
    hp[0] = __floats2half2_rn(w00, w00);
    hp[1] = __floats2half2_rn(w01, w01);
    hp[2] = __floats2half2_rn(w10, w10);
    hp[3] = __floats2half2_rn(w11, w11);
    cwh[p] = wpk;
}

__global__ void __launch_bounds__(256, 3) dcn_fused_kernel(
    const float* __restrict__ ob, const float* __restrict__ bias,
    float* __restrict__ out)
{
    extern __shared__ uint32_t smw[];
    uint32_t sb = (uint32_t)__cvta_generic_to_shared(smw);

    int tid = threadIdx.x, warp = tid >> 5, lane = tid & 31;
    int g = lane >> 2, tg = lane & 3;
    int l = lane & 7, h8 = (lane >> 3) & 1, kh = (lane >> 4) & 1;
    int m = lane >> 3;
    int blk = blockIdx.x, b = blk >> 7, y = blk & 127;

    // ======================= Phase A: offset conv ==========================
    {
        uint32_t a_lane = (uint32_t)((8 * h8 + l) * 36 + 4 * kh) * 4;
        uint32_t b_lane01 = (uint32_t)(9216 * 4) +
            (uint32_t)((8 * (m & 1) + l) * 12 + (m >> 1) * 4) * 4;
        uint32_t b_lane2  = (uint32_t)(9216 * 4) +
            (uint32_t)((8 * h8 + l) * 12 + 8) * 4;

        float acc3[3][4];
        #pragma unroll
        for (int nt = 0; nt < 3; ++nt) {
            int col = 8 * nt + 2 * tg;
            float b0 = (col < 18) ? __ldg(&ob[col]) : 0.f;
            float b1 = (col + 1 < 18) ? __ldg(&ob[col + 1]) : 0.f;
            acc3[nt][0] = b0; acc3[nt][1] = b1;
            acc3[nt][2] = b0; acc3[nt][3] = b1;
        }

        for (int ky = 0; ky < 3; ++ky) {
            int yy = y + ky - 1;
            if (yy < 0 || yy >= Hc) continue;   // uniform per block
            __syncthreads();
            uint4* xd = (uint4*)smw;
            #pragma unroll
            for (int i = 0; i < 5; ++i) {
                int j4 = tid + 256 * i;
                if (j4 < 1040) {
                    int xi = j4 >> 3, cg = j4 & 7, x = xi - 1;
                    uint4 v = make_uint4(0u, 0u, 0u, 0u);
                    if (x >= 0 && x < Wc)
                        v = g_xH4[((size_t)(b * Hc + yy) * Wc + x) * 8 + cg];
                    xd[xi * 9 + cg] = v;
                }
            }
            {
                uint4* od = (uint4*)(smw + 9216);
                #pragma unroll
                for (int i = 0; i < 3; ++i) {
                    int j4 = tid + 256 * i;
                    if (j4 < 576) od[j4] = g_owH4[ky * 576 + j4];
                }
            }
            __syncthreads();
            #pragma unroll
            for (int kx = 0; kx < 3; ++kx) {
                uint32_t abase = sb + (uint32_t)((warp * 16 + kx) * 36) * 4 + a_lane;
                uint32_t bb01  = sb + (uint32_t)(kx * 768) * 4 + b_lane01;
                uint32_t bb2   = sb + (uint32_t)(kx * 768) * 4 + b_lane2;
                #pragma unroll
                for (int kk = 0; kk < 4; ++kk) {
                    uint32_t a[4], bq[4], b2[2];
                    ldsm_x4(a, abase + kk * 32);
                    ldsm_x4t(bq, bb01 + kk * 768);
                    ldsm_x2t(b2, bb2 + kk * 768);
                    mma16(acc3[0], a, bq[0], bq[1]);
                    mma16(acc3[1], a, bq[2], bq[3]);
                    mma16(acc3[2], a, b2[0], b2[1]);
                }
            }
        }
        __syncthreads();
        float2* offs = (float2*)(smw + SM_OFFS);
        #pragma unroll
        for (int nt = 0; nt < 3; ++nt) {
            int col = 8 * nt + 2 * tg;
            if (col < 18) {
                int tap = col >> 1;
                int p = warp * 16 + g;
                offs[tap * 128 + p]     = make_float2(acc3[nt][0], acc3[nt][1]);
                offs[tap * 128 + p + 8] = make_float2(acc3[nt][2], acc3[nt][3]);
            }
        }
        __syncthreads();
    }

    // ======================= Phase B: main conv ============================
    int mgrp = warp >> 1, ngrp = warp & 1;
    int s_cg = tid & 7, s_p0 = tid >> 3;
    const float2* offs = (const float2*)(smw + SM_OFFS);

    uint32_t a_lane = (uint32_t)((mgrp * 32 + 8 * h8 + l) * 36 + 4 * kh) * 4;
    uint32_t b_lane = (uint32_t)((8 * (m & 1) + l) * 36 +
                                 (ngrp * 4 + (m >> 1)) * 4) * 4;

    float acc[2][4][4];
    #pragma unroll
    for (int mt = 0; mt < 2; ++mt)
        #pragma unroll
        for (int nt = 0; nt < 4; ++nt)
            #pragma unroll
            for (int j = 0; j < 4; ++j) acc[mt][nt][j] = 0.f;

    // coords for tap 0 into coordbuf[0]
    if (tid < 128) {
        uint4* cw = (uint4*)(smw + SM_CB);
        int4*  ci = (int4*)(smw + SM_CB + 512);
        compute_coords(0, tid, y, b, offs, cw, ci);
    }
    __syncthreads();

    for (int k = 0; k < 9; ++k) {
        int buf = k & 1;
        // stage weight tile via cp.async (overlaps sampling)
        {
            const uint4* src = g_wH4 + k * 512;
            uint32_t dbase = sb + (uint32_t)(9216 + buf * 2304) * 4;
            #pragma unroll
            for (int i = 0; i < 2; ++i) {
                int j4 = tid + 256 * i;
                int c = j4 >> 3, seg = j4 & 7;
                cp_async16(dbase + (uint32_t)(c * 9 + seg) * 16, src + j4);
            }
            CP_COMMIT();
        }
        // sample into patch[buf] using coordbuf[buf] — fp16 HFMA2 lerp
        {
            const uint4* cw = (const uint4*)(smw + SM_CB + buf * 1024);
            const int4*  ci = (const int4*)(smw + SM_CB + buf * 1024 + 512);
            uint4* pdst = (uint4*)(smw + buf * 4608);
            #pragma unroll
            for (int i = 0; i < 4; ++i) {
                int p = s_p0 + 32 * i;
                uint4 wq = cw[p];
                half2 w00h = ((half2*)&wq)[0];
                half2 w01h = ((half2*)&wq)[1];
                half2 w10h = ((half2*)&wq)[2];
                half2 w11h = ((half2*)&wq)[3];
                int4  c4 = ci[p];
                uint4 q00 = g_xH4[c4.x + s_cg];
                uint4 q01 = g_xH4[c4.y + s_cg];
                uint4 q10 = g_xH4[c4.z + s_cg];
                uint4 q11 = g_xH4[c4.w + s_cg];
                uint4 r;
                half2* hr = (half2*)&r;
                #pragma unroll
                for (int j = 0; j < 4; ++j) {
                    half2 t0 = __hfma2(((half2*)&q01)[j], w01h,
                                       __hmul2(((half2*)&q00)[j], w00h));
                    half2 t1 = __hfma2(((half2*)&q11)[j], w11h,
                                       __hmul2(((half2*)&q10)[j], w10h));
                    hr[j] = __hadd2(t0, t1);
                }
                pdst[p * 9 + s_cg] = r;
            }
        }
        // coords for tap k+1 into coordbuf[buf^1] (before barrier; read after)
        if (k < 8 && tid < 128) {
            uint4* cw = (uint4*)(smw + SM_CB + (buf ^ 1) * 1024);
            int4*  ci = (int4*)(smw + SM_CB + (buf ^ 1) * 1024 + 512);
            compute_coords(k + 1, tid, y, b, offs, cw, ci);
        }
        CP_WAIT0();
        __syncthreads();
        // GEMM via ldmatrix
        {
            uint32_t abase = sb + (uint32_t)(buf * 4608) * 4 + a_lane;
            uint32_t bbase = sb + (uint32_t)((9216 + buf * 2304)) * 4 + b_lane;
            #pragma unroll
            for (int kk = 0; kk < 4; ++kk) {
                uint32_t a0[4], a1[4], bq0[4], bq1[4];
                ldsm_x4(a0, abase + kk * 32);
                ldsm_x4(a1, abase + 2304 + kk * 32);
                ldsm_x4t(bq0, bbase + kk * 2304);
                ldsm_x4t(bq1, bbase + 32 + kk * 2304);
                mma16(acc[0][0], a0, bq0[0], bq0[1]);
                mma16(acc[0][1], a0, bq0[2], bq0[3]);
                mma16(acc[0][2], a0, bq1[0], bq1[1]);
                mma16(acc[0][3], a0, bq1[2], bq1[3]);
                mma16(acc[1][0], a1, bq0[0], bq0[1]);
                mma16(acc[1][1], a1, bq0[2], bq0[3]);
                mma16(acc[1][2], a1, bq1[0], bq1[1]);
                mma16(acc[1][3], a1, bq1[2], bq1[3]);
            }
        }
    }

    // epilogue: transpose through smem (stride 132 floats), add bias, store
    __syncthreads();
    float* O = (float*)smw;
    #pragma unroll
    for (int mt = 0; mt < 2; ++mt)
        #pragma unroll
        for (int nt = 0; nt < 4; ++nt) {
            int row = mgrp * 32 + 16 * mt + g;
            int col = ngrp * 32 + 8 * nt + 2 * tg;
            float b0 = __ldg(&bias[col]), b1 = __ldg(&bias[col + 1]);
            O[col * 132 + row]           = acc[mt][nt][0] + b0;
            O[(col + 1) * 132 + row]     = acc[mt][nt][1] + b1;
            O[col * 132 + row + 8]       = acc[mt][nt][2] + b0;
            O[(col + 1) * 132 + row + 8] = acc[mt][nt][3] + b1;
        }
    __syncthreads();
    #pragma unroll
    for (int i = 0; i < 8; ++i) {
        int j4 = tid + 256 * i;
        int co = j4 >> 5, xq = j4 & 31;
        float4 v = *(float4*)&O[co * 132 + xq * 4];
        *(float4*)&out[(((size_t)b * COUTc + co) * Hc + y) * Wc + xq * 4] = v;
    }
}

// ---------------------------------------------------------------------------
extern "C" void kernel_launch(void* const* d_in, const int* in_sizes, int n_in,
                              void* d_out, int out_size)
{
    const float* x      = (const float*)d_in[0];
    const float* weight = (const float*)d_in[1];
    const float* bias   = (const float*)d_in[2];
    const float* ow     = (const float*)d_in[3];
    const float* ob     = (const float*)d_in[4];
    float* out = (float*)d_out;

    static int configured = 0;
    if (!configured) {
        cudaFuncSetAttribute(dcn_fused_kernel,
            cudaFuncAttributeMaxDynamicSharedMemorySize, 18176 * 4);
        configured = 1;
    }

    prep_kernel<<<512 + 36, 256>>>(x, weight, ow);
    dcn_fused_kernel<<<Bc * Hc, 256, 18176 * 4>>>(ob, bias, out);
}